// round 1
// baseline (speedup 1.0000x reference)
#include <cuda_runtime.h>
#include <cuda_bf16.h>
#include <cstdint>

#define L      2048
#define DM     512
#define DI     1024
#define NST    16
#define NC     64           // scan chunks
#define TCH    (L / NC)     // 32 steps per chunk

// ------------------------- scratch (__device__ globals, no alloc) ----------
__device__ float g_xz[2][L * 2 * DI];        // in-proj output per dir
__device__ float g_xc[2][L * DI];            // conv output
__device__ float g_sxc[2][L * DI];           // silu(conv output)
__device__ float g_delta[2][L * DI];         // sp[:, :1024]
__device__ float g_BC[2][L * 32];            // sp[:, 1024:1056] (B|C)
__device__ float g_dt[2][L * DI];            // softplus(delta@dtW+b)
__device__ float g_u[2][L * DI];             // y * silu(z)
__device__ float g_cat[L * 2 * DM];          // [out_fwd | out_bwd(rev)]
__device__ float g_aprod[2][NC * DI * NST];
__device__ float g_hpart[2][NC * DI * NST];
__device__ float g_hinit[2][NC * DI * NST];

// ------------------------- main SGEMM: 128x128 tile, 8x8/thread -----------
// C[orow, colOff+col] = A[(rev?)row, :] @ B[:, col] + bias[col]  (+softplus)
template <int EPI>
__global__ __launch_bounds__(256, 2)
void sgemm128(const float* __restrict__ A, int lda, int revA,
              const float* __restrict__ B, int ldb,
              const float* __restrict__ bias,
              float* __restrict__ C, int ldc, int revC, int colOff,
              int M, int K)
{
    __shared__ __align__(16) float As[8][128];
    __shared__ __align__(16) float Bs[8][128];

    const int tid = threadIdx.x;
    const int bx = blockIdx.x, by = blockIdx.y;

    const int aRow = tid >> 1;            // 0..127
    const int aCol = (tid & 1) * 4;       // 0 or 4
    const int bRow = tid >> 5;            // 0..7
    const int bCol = (tid & 31) * 4;      // 0..124
    const int trow = (tid >> 4) * 8;      // 0..120
    const int tcol = (tid & 15) * 8;      // 0..120

    int gar = by * 128 + aRow;
    if (revA) gar = M - 1 - gar;
    const float* Aptr = A + (size_t)gar * lda + aCol;
    const float* Bptr = B + (size_t)bRow * ldb + bx * 128 + bCol;

    float acc[8][8];
    #pragma unroll
    for (int i = 0; i < 8; i++)
        #pragma unroll
        for (int j = 0; j < 8; j++) acc[i][j] = 0.f;

    for (int k0 = 0; k0 < K; k0 += 8) {
        float4 av = *(const float4*)(Aptr + k0);
        float4 bv = *(const float4*)(Bptr + (size_t)k0 * ldb);
        As[aCol + 0][aRow] = av.x;
        As[aCol + 1][aRow] = av.y;
        As[aCol + 2][aRow] = av.z;
        As[aCol + 3][aRow] = av.w;
        *(float4*)&Bs[bRow][bCol] = bv;
        __syncthreads();

        #pragma unroll
        for (int kk = 0; kk < 8; kk++) {
            float rm[8], rn[8];
            *(float4*)(rm)     = *(const float4*)&As[kk][trow];
            *(float4*)(rm + 4) = *(const float4*)&As[kk][trow + 4];
            *(float4*)(rn)     = *(const float4*)&Bs[kk][tcol];
            *(float4*)(rn + 4) = *(const float4*)&Bs[kk][tcol + 4];
            #pragma unroll
            for (int i = 0; i < 8; i++)
                #pragma unroll
                for (int j = 0; j < 8; j++)
                    acc[i][j] += rm[i] * rn[j];
        }
        __syncthreads();
    }

    #pragma unroll
    for (int i = 0; i < 8; i++) {
        int row = by * 128 + trow + i;
        int orow = revC ? (M - 1 - row) : row;
        float* crow = C + (size_t)orow * ldc + colOff;
        #pragma unroll
        for (int j = 0; j < 8; j++) {
            int col = bx * 128 + tcol + j;
            float v = acc[i][j] + bias[col];
            if (EPI == 1) v = (v > 15.f) ? v : log1pf(__expf(v));
            crow[col] = v;
        }
    }
}

// ------------------------- small N=32 GEMM (B,C projection) ---------------
__global__ void sgemm_n32(const float* __restrict__ A, int lda,
                          const float* __restrict__ B, int ldb,
                          const float* __restrict__ bias,
                          float* __restrict__ C, int ldc, int K)
{
    __shared__ float Bs[32][33];
    __shared__ float As[8][33];
    const int r = threadIdx.x >> 5;   // 0..7
    const int c = threadIdx.x & 31;   // 0..31
    const int row0 = blockIdx.x * 8;
    float acc = 0.f;
    for (int k0 = 0; k0 < K; k0 += 32) {
        #pragma unroll
        for (int i = r; i < 32; i += 8) Bs[i][c] = B[(size_t)(k0 + i) * ldb + c];
        As[r][c] = A[(size_t)(row0 + r) * lda + k0 + c];
        __syncthreads();
        #pragma unroll
        for (int kk = 0; kk < 32; kk++) acc += As[r][kk] * Bs[kk][c];
        __syncthreads();
    }
    C[(size_t)(row0 + r) * ldc + c] = acc + bias[c];
}

// ------------------------- causal depthwise conv (K=4) + silu -------------
__global__ void conv_silu_kernel(const float* __restrict__ cw_f,
                                 const float* __restrict__ cb_f,
                                 const float* __restrict__ cw_b,
                                 const float* __restrict__ cb_b)
{
    const int dir = blockIdx.z;
    const int idx = blockIdx.x * blockDim.x + threadIdx.x;  // 0..L*DI-1
    const int l = idx >> 10;
    const int d = idx & (DI - 1);
    const float* xz = g_xz[dir];
    const float* w = dir ? cw_b : cw_f;
    const float* b = dir ? cb_b : cb_f;
    float s = b[d];
    #pragma unroll
    for (int k = 0; k < 4; k++) {
        int ls = l - 3 + k;
        if (ls >= 0) s += xz[(size_t)ls * (2 * DI) + d] * w[d * 4 + k];
    }
    g_xc[dir][idx] = s;
    g_sxc[dir][idx] = s / (1.f + __expf(-s));
}

// ------------------------- chunked scan --------------------------------
// block: 256 = 16 d-channels x 16 states; grid (NC, DI/16, 2)
__global__ void scan_phaseA(const float* __restrict__ A_log)
{
    const int dir = blockIdx.z;
    const int s = threadIdx.x & 15;
    const int dl = threadIdx.x >> 4;
    const int d = blockIdx.y * 16 + dl;
    const int c = blockIdx.x;
    const float Av = -__expf(A_log[d * NST + s]);
    const float* dtp = g_dt[dir];
    const float* xp = g_xc[dir];
    const float* bc = g_BC[dir];
    float h = 0.f, ap = 1.f;
    int l = c * TCH;
    #pragma unroll 4
    for (int t = 0; t < TCH; t++, l++) {
        float dtv = dtp[l * DI + d];
        float xv = xp[l * DI + d];
        float Bv = bc[l * 32 + s];
        float a = __expf(dtv * Av);
        h = a * h + dtv * Bv * xv;
        ap *= a;
    }
    const int o = (c << 14) + (d << 4) + s;   // (c*DI + d)*16 + s
    g_aprod[dir][o] = ap;
    g_hpart[dir][o] = h;
}

__global__ void scan_phaseB()
{
    const int idx = blockIdx.x * blockDim.x + threadIdx.x;  // 0..2*DI*16-1
    const int dir = idx >> 14;
    const int ds = idx & 16383;
    float h = 0.f;
    for (int c = 0; c < NC; c++) {
        const int o = (c << 14) + ds;
        g_hinit[dir][o] = h;
        h = g_aprod[dir][o] * h + g_hpart[dir][o];
    }
}

__global__ void scan_phaseC(const float* __restrict__ A_log,
                            const float* __restrict__ Dp)
{
    const int dir = blockIdx.z;
    const int s = threadIdx.x & 15;
    const int dl = threadIdx.x >> 4;
    const int d = blockIdx.y * 16 + dl;
    const int c = blockIdx.x;
    const float Av = -__expf(A_log[d * NST + s]);
    const float Dv = Dp[d];
    const float* dtp = g_dt[dir];
    const float* xp = g_xc[dir];
    const float* bc = g_BC[dir];
    const float* xz = g_xz[dir];
    float h = g_hinit[dir][(c << 14) + (d << 4) + s];
    int l = c * TCH;
    for (int t = 0; t < TCH; t++, l++) {
        float dtv = dtp[l * DI + d];
        float xv = xp[l * DI + d];
        float Bv = bc[l * 32 + s];
        float Cv = bc[l * 32 + 16 + s];
        float a = __expf(dtv * Av);
        h = a * h + dtv * Bv * xv;
        float val = h * Cv;
        val += __shfl_xor_sync(0xffffffffu, val, 1);
        val += __shfl_xor_sync(0xffffffffu, val, 2);
        val += __shfl_xor_sync(0xffffffffu, val, 4);
        val += __shfl_xor_sync(0xffffffffu, val, 8);
        if (s == 0) {
            float y = val + Dv * xv;
            float zv = xz[(size_t)l * (2 * DI) + DI + d];
            g_u[dir][l * DI + d] = y * (zv / (1.f + __expf(-zv)));
        }
    }
}

// ------------------------- host launcher --------------------------------
extern "C" void kernel_launch(void* const* d_in, const int* in_sizes, int n_in,
                              void* d_out, int out_size)
{
    (void)in_sizes; (void)n_in; (void)out_size;
    const float* x = (const float*)d_in[0];
    // per-dir param pointers: [dir][param]
    const float* inW[2]  = { (const float*)d_in[1],  (const float*)d_in[11] };
    const float* inb[2]  = { (const float*)d_in[2],  (const float*)d_in[12] };
    const float* cw[2]   = { (const float*)d_in[3],  (const float*)d_in[13] };
    const float* cb[2]   = { (const float*)d_in[4],  (const float*)d_in[14] };
    const float* xpW[2]  = { (const float*)d_in[5],  (const float*)d_in[15] };
    const float* xpb[2]  = { (const float*)d_in[6],  (const float*)d_in[16] };
    const float* dtW[2]  = { (const float*)d_in[7],  (const float*)d_in[17] };
    const float* dtb[2]  = { (const float*)d_in[8],  (const float*)d_in[18] };
    const float* outW[2] = { (const float*)d_in[9],  (const float*)d_in[19] };
    const float* outb[2] = { (const float*)d_in[10], (const float*)d_in[20] };
    const float* A_log   = (const float*)d_in[21];
    const float* Dp      = (const float*)d_in[22];
    const float* fuW     = (const float*)d_in[23];
    const float* fub     = (const float*)d_in[24];
    float* out = (float*)d_out;

    float *xz, *sxc, *delta, *bcb, *dtb_, *ub, *catb;
    cudaGetSymbolAddress((void**)&xz,    g_xz);
    cudaGetSymbolAddress((void**)&sxc,   g_sxc);
    cudaGetSymbolAddress((void**)&delta, g_delta);
    cudaGetSymbolAddress((void**)&bcb,   g_BC);
    cudaGetSymbolAddress((void**)&dtb_,  g_dt);
    cudaGetSymbolAddress((void**)&ub,    g_u);
    cudaGetSymbolAddress((void**)&catb,  g_cat);

    const dim3 blk(256);

    // 1. in-projection: xz[dir] = x(rev for bwd) @ inW + inb   [2048 x 2048]
    for (int dir = 0; dir < 2; dir++) {
        sgemm128<0><<<dim3(2 * DI / 128, L / 128), blk>>>(
            x, DM, dir, inW[dir], 2 * DI, inb[dir],
            xz + (size_t)dir * L * 2 * DI, 2 * DI, 0, 0, L, DM);
    }

    // 2. causal conv + silu
    conv_silu_kernel<<<dim3(L * DI / 256, 1, 2), blk>>>(cw[0], cb[0], cw[1], cb[1]);

    // 3. xp projection split: delta (N=1024) + BC (N=32)
    for (int dir = 0; dir < 2; dir++) {
        sgemm128<0><<<dim3(DI / 128, L / 128), blk>>>(
            sxc + (size_t)dir * L * DI, DI, 0, xpW[dir], DI + 2 * NST, xpb[dir],
            delta + (size_t)dir * L * DI, DI, 0, 0, L, DI);
        sgemm_n32<<<L / 8, blk>>>(
            sxc + (size_t)dir * L * DI, DI, xpW[dir] + DI, DI + 2 * NST,
            xpb[dir] + DI, bcb + (size_t)dir * L * 32, 32, DI);
    }

    // 4. dt = softplus(delta @ dtW + dtb)
    for (int dir = 0; dir < 2; dir++) {
        sgemm128<1><<<dim3(DI / 128, L / 128), blk>>>(
            delta + (size_t)dir * L * DI, DI, 0, dtW[dir], DI, dtb[dir],
            dtb_ + (size_t)dir * L * DI, DI, 0, 0, L, DI);
    }

    // 5. chunked selective scan -> u = y * silu(z)
    scan_phaseA<<<dim3(NC, DI / 16, 2), blk>>>(A_log);
    scan_phaseB<<<2 * DI * NST / 256, blk>>>();
    scan_phaseC<<<dim3(NC, DI / 16, 2), blk>>>(A_log, Dp);

    // 6. out projection -> cat buffer (bwd rows reversed, col offset 512)
    for (int dir = 0; dir < 2; dir++) {
        sgemm128<0><<<dim3(DM / 128, L / 128), blk>>>(
            ub + (size_t)dir * L * DI, DI, 0, outW[dir], DM, outb[dir],
            catb, 2 * DM, dir, dir * DM, L, DI);
    }

    // 7. fusion: out = cat @ fusion_W + fusion_b
    sgemm128<0><<<dim3(DM / 128, L / 128), blk>>>(
        catb, 2 * DM, 0, fuW, DM, fub, out, DM, 0, 0, L, 2 * DM);
}

// round 2
// speedup vs baseline: 2.3608x; 2.3608x over previous
#include <cuda_runtime.h>
#include <cuda_bf16.h>
#include <cstdint>

#define L      2048
#define DM     512
#define DI     1024
#define NST    16
#define NC     64           // scan chunks
#define TCH    (L / NC)     // 32 steps per chunk

// ------------------------- scratch (__device__ globals, no alloc) ----------
__device__ float g_xz[2][L * 2 * DI];        // in-proj output per dir
__device__ float g_xc[2][L * DI];            // conv output
__device__ float g_sxc[2][L * DI];           // silu(conv output)
__device__ float g_delta[2][L * DI];         // sp[:, :1024]
__device__ float g_BC[2][L * 32];            // sp[:, 1024:1056] (B|C)
__device__ float g_dt[2][L * DI];            // softplus(delta@dtW+b)
__device__ float g_u[2][L * DI];             // y * silu(z)
__device__ float g_cat[L * 2 * DM];          // [out_fwd | out_bwd(rev)]
__device__ float g_aprod[2][NC * DI * NST];
__device__ float g_hpart[2][NC * DI * NST];
__device__ float g_hinit[2][NC * DI * NST];

// ------------------------- tf32 helpers -----------------------------------
__device__ __forceinline__ uint32_t f2t(float f) {
    uint32_t u;
    asm("cvt.rna.tf32.f32 %0, %1;" : "=r"(u) : "f"(f));
    return u;
}

__device__ __forceinline__ void mma_tf32(float* c, const uint32_t* a, const uint32_t* b) {
    asm volatile(
        "mma.sync.aligned.m16n8k8.row.col.f32.tf32.tf32.f32 "
        "{%0,%1,%2,%3}, {%4,%5,%6,%7}, {%8,%9}, {%0,%1,%2,%3};\n"
        : "+f"(c[0]), "+f"(c[1]), "+f"(c[2]), "+f"(c[3])
        : "r"(a[0]), "r"(a[1]), "r"(a[2]), "r"(a[3]), "r"(b[0]), "r"(b[1]));
}

// ------------------------- tensor-core GEMM: 128x128x32 --------------------
// C[orow, colOff+col] = A[(rev?)row,:] @ B[:,col] + bias[col]  (+softplus)
// grid = (N/128, M/128); 256 threads; warp tile 64x32 (4x4 m16n8k8 tiles)
template <int EPI>
__global__ __launch_bounds__(256, 1)
void tgemm(const float* __restrict__ A, int lda, int revA,
           const float* __restrict__ B, int ldb,
           const float* __restrict__ bias,
           float* __restrict__ C, int ldc, int revC, int colOff,
           int M, int K)
{
    __shared__ __align__(16) uint32_t As[128][36];   // [m][k], pad 4
    __shared__ __align__(16) uint32_t Bs[32][136];   // [k][n], pad 8

    const int tid  = threadIdx.x;
    const int lane = tid & 31;
    const int warp = tid >> 5;
    const int wm = warp & 1;      // 2 warps in M
    const int wn = warp >> 1;     // 4 warps in N
    const int g  = lane >> 2;     // 0..7
    const int cc = lane & 3;      // 0..3
    const int bx = blockIdx.x, by = blockIdx.y;

    // --- gmem load mapping ---
    // A: per chunk ch: row = (tid>>3)+32*ch, kq = tid&7  (float4 along K)
    const int aRow = tid >> 3;
    const int aKq  = tid & 7;
    const float* aPtr[4];
    #pragma unroll
    for (int ch = 0; ch < 4; ch++) {
        int row = by * 128 + aRow + 32 * ch;
        int gar = revA ? (M - 1 - row) : row;
        aPtr[ch] = A + (size_t)gar * lda + aKq * 4;
    }
    // B: per chunk ch: k = (tid>>5)+8*ch, nq = tid&31
    const float* bPtr = B + (size_t)(tid >> 5) * ldb + bx * 128 + (tid & 31) * 4;

    float4 pa[4], pb[4];
    auto loadg = [&](int k0) {
        #pragma unroll
        for (int ch = 0; ch < 4; ch++)
            pa[ch] = *(const float4*)(aPtr[ch] + k0);
        #pragma unroll
        for (int ch = 0; ch < 4; ch++)
            pb[ch] = *(const float4*)(bPtr + (size_t)(k0 + 8 * ch) * ldb);
    };
    auto stores = [&]() {
        #pragma unroll
        for (int ch = 0; ch < 4; ch++) {
            uint4 u = make_uint4(f2t(pa[ch].x), f2t(pa[ch].y), f2t(pa[ch].z), f2t(pa[ch].w));
            *(uint4*)&As[aRow + 32 * ch][aKq * 4] = u;
        }
        #pragma unroll
        for (int ch = 0; ch < 4; ch++) {
            uint4 u = make_uint4(f2t(pb[ch].x), f2t(pb[ch].y), f2t(pb[ch].z), f2t(pb[ch].w));
            *(uint4*)&Bs[(tid >> 5) + 8 * ch][(tid & 31) * 4] = u;
        }
    };

    float acc[4][4][4];
    #pragma unroll
    for (int mt = 0; mt < 4; mt++)
        #pragma unroll
        for (int nt = 0; nt < 4; nt++)
            #pragma unroll
            for (int i = 0; i < 4; i++) acc[mt][nt][i] = 0.f;

    loadg(0);
    stores();
    __syncthreads();

    const int nIt = K / 32;
    for (int it = 0; it < nIt; ++it) {
        if (it + 1 < nIt) loadg((it + 1) * 32);

        #pragma unroll
        for (int ks = 0; ks < 32; ks += 8) {
            uint32_t a[4][4], b[4][2];
            #pragma unroll
            for (int mt = 0; mt < 4; mt++) {
                const uint32_t* p0 = &As[wm * 64 + mt * 16 + g][ks + cc];
                const uint32_t* p1 = &As[wm * 64 + mt * 16 + g + 8][ks + cc];
                a[mt][0] = p0[0]; a[mt][2] = p0[4];
                a[mt][1] = p1[0]; a[mt][3] = p1[4];
            }
            #pragma unroll
            for (int nt = 0; nt < 4; nt++) {
                b[nt][0] = Bs[ks + cc][wn * 32 + nt * 8 + g];
                b[nt][1] = Bs[ks + cc + 4][wn * 32 + nt * 8 + g];
            }
            #pragma unroll
            for (int mt = 0; mt < 4; mt++)
                #pragma unroll
                for (int nt = 0; nt < 4; nt++)
                    mma_tf32(acc[mt][nt], a[mt], b[nt]);
        }

        __syncthreads();
        if (it + 1 < nIt) {
            stores();
        }
        __syncthreads();
    }

    // --- epilogue ---
    #pragma unroll
    for (int mt = 0; mt < 4; mt++) {
        int r0 = by * 128 + wm * 64 + mt * 16 + g;
        int r1 = r0 + 8;
        int or0 = revC ? (M - 1 - r0) : r0;
        int or1 = revC ? (M - 1 - r1) : r1;
        float* crow0 = C + (size_t)or0 * ldc + colOff;
        float* crow1 = C + (size_t)or1 * ldc + colOff;
        #pragma unroll
        for (int nt = 0; nt < 4; nt++) {
            int col = bx * 128 + wn * 32 + nt * 8 + 2 * cc;
            float b0 = bias[col], b1 = bias[col + 1];
            float v00 = acc[mt][nt][0] + b0, v01 = acc[mt][nt][1] + b1;
            float v10 = acc[mt][nt][2] + b0, v11 = acc[mt][nt][3] + b1;
            if (EPI == 1) {
                v00 = (v00 > 15.f) ? v00 : log1pf(__expf(v00));
                v01 = (v01 > 15.f) ? v01 : log1pf(__expf(v01));
                v10 = (v10 > 15.f) ? v10 : log1pf(__expf(v10));
                v11 = (v11 > 15.f) ? v11 : log1pf(__expf(v11));
            }
            *(float2*)&crow0[col] = make_float2(v00, v01);
            *(float2*)&crow1[col] = make_float2(v10, v11);
        }
    }
}

// ------------------------- small N=32 GEMM (B,C projection) ---------------
__global__ void sgemm_n32(const float* __restrict__ A, int lda,
                          const float* __restrict__ B, int ldb,
                          const float* __restrict__ bias,
                          float* __restrict__ C, int ldc, int K)
{
    __shared__ float Bs[32][33];
    __shared__ float As[8][33];
    const int r = threadIdx.x >> 5;   // 0..7
    const int c = threadIdx.x & 31;   // 0..31
    const int row0 = blockIdx.x * 8;
    float acc = 0.f;
    for (int k0 = 0; k0 < K; k0 += 32) {
        #pragma unroll
        for (int i = r; i < 32; i += 8) Bs[i][c] = B[(size_t)(k0 + i) * ldb + c];
        As[r][c] = A[(size_t)(row0 + r) * lda + k0 + c];
        __syncthreads();
        #pragma unroll
        for (int kk = 0; kk < 32; kk++) acc += As[r][kk] * Bs[kk][c];
        __syncthreads();
    }
    C[(size_t)(row0 + r) * ldc + c] = acc + bias[c];
}

// ------------------------- causal depthwise conv (K=4) + silu -------------
__global__ void conv_silu_kernel(const float* __restrict__ cw_f,
                                 const float* __restrict__ cb_f,
                                 const float* __restrict__ cw_b,
                                 const float* __restrict__ cb_b)
{
    const int dir = blockIdx.z;
    const int idx = blockIdx.x * blockDim.x + threadIdx.x;  // 0..L*DI-1
    const int l = idx >> 10;
    const int d = idx & (DI - 1);
    const float* xz = g_xz[dir];
    const float* w = dir ? cw_b : cw_f;
    const float* b = dir ? cb_b : cb_f;
    float s = b[d];
    #pragma unroll
    for (int k = 0; k < 4; k++) {
        int ls = l - 3 + k;
        if (ls >= 0) s += xz[(size_t)ls * (2 * DI) + d] * w[d * 4 + k];
    }
    g_xc[dir][idx] = s;
    g_sxc[dir][idx] = s / (1.f + __expf(-s));
}

// ------------------------- chunked scan --------------------------------
__global__ void scan_phaseA(const float* __restrict__ A_log)
{
    const int dir = blockIdx.z;
    const int s = threadIdx.x & 15;
    const int dl = threadIdx.x >> 4;
    const int d = blockIdx.y * 16 + dl;
    const int c = blockIdx.x;
    const float Av = -__expf(A_log[d * NST + s]);
    const float* dtp = g_dt[dir];
    const float* xp = g_xc[dir];
    const float* bc = g_BC[dir];
    float h = 0.f, ap = 1.f;
    int l = c * TCH;
    #pragma unroll 4
    for (int t = 0; t < TCH; t++, l++) {
        float dtv = dtp[l * DI + d];
        float xv = xp[l * DI + d];
        float Bv = bc[l * 32 + s];
        float a = __expf(dtv * Av);
        h = a * h + dtv * Bv * xv;
        ap *= a;
    }
    const int o = (c << 14) + (d << 4) + s;
    g_aprod[dir][o] = ap;
    g_hpart[dir][o] = h;
}

__global__ void scan_phaseB()
{
    const int idx = blockIdx.x * blockDim.x + threadIdx.x;  // 0..2*DI*16-1
    const int dir = idx >> 14;
    const int ds = idx & 16383;
    float h = 0.f;
    for (int c = 0; c < NC; c++) {
        const int o = (c << 14) + ds;
        g_hinit[dir][o] = h;
        h = g_aprod[dir][o] * h + g_hpart[dir][o];
    }
}

__global__ void scan_phaseC(const float* __restrict__ A_log,
                            const float* __restrict__ Dp)
{
    const int dir = blockIdx.z;
    const int s = threadIdx.x & 15;
    const int dl = threadIdx.x >> 4;
    const int d = blockIdx.y * 16 + dl;
    const int c = blockIdx.x;
    const float Av = -__expf(A_log[d * NST + s]);
    const float Dv = Dp[d];
    const float* dtp = g_dt[dir];
    const float* xp = g_xc[dir];
    const float* bc = g_BC[dir];
    const float* xz = g_xz[dir];
    float h = g_hinit[dir][(c << 14) + (d << 4) + s];
    int l = c * TCH;
    for (int t = 0; t < TCH; t++, l++) {
        float dtv = dtp[l * DI + d];
        float xv = xp[l * DI + d];
        float Bv = bc[l * 32 + s];
        float Cv = bc[l * 32 + 16 + s];
        float a = __expf(dtv * Av);
        h = a * h + dtv * Bv * xv;
        float val = h * Cv;
        val += __shfl_xor_sync(0xffffffffu, val, 1);
        val += __shfl_xor_sync(0xffffffffu, val, 2);
        val += __shfl_xor_sync(0xffffffffu, val, 4);
        val += __shfl_xor_sync(0xffffffffu, val, 8);
        if (s == 0) {
            float y = val + Dv * xv;
            float zv = xz[(size_t)l * (2 * DI) + DI + d];
            g_u[dir][l * DI + d] = y * (zv / (1.f + __expf(-zv)));
        }
    }
}

// ------------------------- host launcher --------------------------------
extern "C" void kernel_launch(void* const* d_in, const int* in_sizes, int n_in,
                              void* d_out, int out_size)
{
    (void)in_sizes; (void)n_in; (void)out_size;
    const float* x = (const float*)d_in[0];
    const float* inW[2]  = { (const float*)d_in[1],  (const float*)d_in[11] };
    const float* inb[2]  = { (const float*)d_in[2],  (const float*)d_in[12] };
    const float* cw[2]   = { (const float*)d_in[3],  (const float*)d_in[13] };
    const float* cb[2]   = { (const float*)d_in[4],  (const float*)d_in[14] };
    const float* xpW[2]  = { (const float*)d_in[5],  (const float*)d_in[15] };
    const float* xpb[2]  = { (const float*)d_in[6],  (const float*)d_in[16] };
    const float* dtW[2]  = { (const float*)d_in[7],  (const float*)d_in[17] };
    const float* dtb[2]  = { (const float*)d_in[8],  (const float*)d_in[18] };
    const float* outW[2] = { (const float*)d_in[9],  (const float*)d_in[19] };
    const float* outb[2] = { (const float*)d_in[10], (const float*)d_in[20] };
    const float* A_log   = (const float*)d_in[21];
    const float* Dp      = (const float*)d_in[22];
    const float* fuW     = (const float*)d_in[23];
    const float* fub     = (const float*)d_in[24];
    float* out = (float*)d_out;

    float *xz, *sxc, *delta, *bcb, *dtb_, *ub, *catb;
    cudaGetSymbolAddress((void**)&xz,    g_xz);
    cudaGetSymbolAddress((void**)&sxc,   g_sxc);
    cudaGetSymbolAddress((void**)&delta, g_delta);
    cudaGetSymbolAddress((void**)&bcb,   g_BC);
    cudaGetSymbolAddress((void**)&dtb_,  g_dt);
    cudaGetSymbolAddress((void**)&ub,    g_u);
    cudaGetSymbolAddress((void**)&catb,  g_cat);

    const dim3 blk(256);

    // 1. in-projection: xz[dir] = x(rev for bwd) @ inW + inb   [2048 x 2048]
    for (int dir = 0; dir < 2; dir++) {
        tgemm<0><<<dim3(2 * DI / 128, L / 128), blk>>>(
            x, DM, dir, inW[dir], 2 * DI, inb[dir],
            xz + (size_t)dir * L * 2 * DI, 2 * DI, 0, 0, L, DM);
    }

    // 2. causal conv + silu
    conv_silu_kernel<<<dim3(L * DI / 256, 1, 2), blk>>>(cw[0], cb[0], cw[1], cb[1]);

    // 3. xp projection split: delta (N=1024) + BC (N=32)
    for (int dir = 0; dir < 2; dir++) {
        tgemm<0><<<dim3(DI / 128, L / 128), blk>>>(
            sxc + (size_t)dir * L * DI, DI, 0, xpW[dir], DI + 2 * NST, xpb[dir],
            delta + (size_t)dir * L * DI, DI, 0, 0, L, DI);
        sgemm_n32<<<L / 8, blk>>>(
            sxc + (size_t)dir * L * DI, DI, xpW[dir] + DI, DI + 2 * NST,
            xpb[dir] + DI, bcb + (size_t)dir * L * 32, 32, DI);
    }

    // 4. dt = softplus(delta @ dtW + dtb)
    for (int dir = 0; dir < 2; dir++) {
        tgemm<1><<<dim3(DI / 128, L / 128), blk>>>(
            delta + (size_t)dir * L * DI, DI, 0, dtW[dir], DI, dtb[dir],
            dtb_ + (size_t)dir * L * DI, DI, 0, 0, L, DI);
    }

    // 5. chunked selective scan -> u = y * silu(z)
    scan_phaseA<<<dim3(NC, DI / 16, 2), blk>>>(A_log);
    scan_phaseB<<<2 * DI * NST / 256, blk>>>();
    scan_phaseC<<<dim3(NC, DI / 16, 2), blk>>>(A_log, Dp);

    // 6. out projection -> cat buffer (bwd rows reversed, col offset 512)
    for (int dir = 0; dir < 2; dir++) {
        tgemm<0><<<dim3(DM / 128, L / 128), blk>>>(
            ub + (size_t)dir * L * DI, DI, 0, outW[dir], DM, outb[dir],
            catb, 2 * DM, dir, dir * DM, L, DI);
    }

    // 7. fusion: out = cat @ fusion_W + fusion_b
    tgemm<0><<<dim3(DM / 128, L / 128), blk>>>(
        catb, 2 * DM, 0, fuW, DM, fub, out, DM, 0, 0, L, 2 * DM);
}

// round 3
// speedup vs baseline: 2.4860x; 1.0530x over previous
#include <cuda_runtime.h>
#include <cuda_bf16.h>
#include <cstdint>

#define L      2048
#define DM     512
#define DI     1024
#define NST    16
#define NC     64           // scan chunks
#define TCH    (L / NC)     // 32 steps per chunk

// ------------------------- scratch (__device__ globals, no alloc) ----------
__device__ float g_xz[2][L * 2 * DI];        // in-proj output per dir
__device__ float g_xc[2][L * DI];            // conv output
__device__ float g_sxc[2][L * DI];           // silu(conv) [tf32-rounded]
__device__ float g_delta[2][L * DI];         // sp[:, :1024] [tf32-rounded]
__device__ float g_BC[2][L * 32];            // sp[:, 1024:1056] (B|C)
__device__ float g_dt[2][L * DI];            // softplus(delta@dtW+b)
__device__ float g_u[2][L * DI];             // y * silu(z) [tf32-rounded]
__device__ float g_cat[L * 2 * DM];          // [out_fwd | out_bwd(rev)] [rounded]
__device__ float g_aprod[2][NC * DI * NST];
__device__ float g_hpart[2][NC * DI * NST];
__device__ float g_hinit[2][NC * DI * NST];

// tf32-rounded copies of x + weights
#define OFF_X      0
#define OFF_INW0   (OFF_X    + L * DM)
#define OFF_INW1   (OFF_INW0 + DM * 2 * DI)
#define OFF_XPW0   (OFF_INW1 + DM * 2 * DI)
#define OFF_XPW1   (OFF_XPW0 + DI * 1056)
#define OFF_DTW0   (OFF_XPW1 + DI * 1056)
#define OFF_DTW1   (OFF_DTW0 + DI * DI)
#define OFF_OUTW0  (OFF_DTW1 + DI * DI)
#define OFF_OUTW1  (OFF_OUTW0 + DI * DM)
#define OFF_FUW    (OFF_OUTW1 + DI * DM)
#define WR_TOTAL   (OFF_FUW   + 2 * DM * DM)
__device__ float g_wr[WR_TOTAL];

// ------------------------- tf32 helpers -----------------------------------
__device__ __forceinline__ uint32_t f2t(float f) {
    uint32_t u;
    asm("cvt.rna.tf32.f32 %0, %1;" : "=r"(u) : "f"(f));
    return u;
}

__device__ __forceinline__ void mma_tf32(float* c, const uint32_t* a, const uint32_t* b) {
    asm volatile(
        "mma.sync.aligned.m16n8k8.row.col.f32.tf32.tf32.f32 "
        "{%0,%1,%2,%3}, {%4,%5,%6,%7}, {%8,%9}, {%0,%1,%2,%3};\n"
        : "+f"(c[0]), "+f"(c[1]), "+f"(c[2]), "+f"(c[3])
        : "r"(a[0]), "r"(a[1]), "r"(a[2]), "r"(a[3]), "r"(b[0]), "r"(b[1]));
}

__device__ __forceinline__ void cpa16(void* s, const void* g) {
    uint32_t sa = (uint32_t)__cvta_generic_to_shared(s);
    asm volatile("cp.async.cg.shared.global [%0], [%1], 16;" :: "r"(sa), "l"(g));
}
__device__ __forceinline__ void cpa_commit() {
    asm volatile("cp.async.commit_group;" ::: "memory");
}
__device__ __forceinline__ void cpa_wait0() {
    asm volatile("cp.async.wait_group 0;" ::: "memory");
}

// ------------------------- round-to-tf32 pre-pass --------------------------
struct RArgs { const float* s[10]; float* d[10]; int n[10]; };

__global__ void round_tf32_kernel(RArgs ra)
{
    const int e = blockIdx.y;
    const int i = (blockIdx.x * 256 + threadIdx.x) * 4;
    if (i >= ra.n[e]) return;
    float4 v = *(const float4*)(ra.s[e] + i);
    uint4 u = make_uint4(f2t(v.x), f2t(v.y), f2t(v.z), f2t(v.w));
    *(uint4*)(ra.d[e] + i) = u;
}

// ------------------------- tensor-core GEMM (cp.async pipelined) -----------
// EPI: 0=none, 1=softplus, 2=round-to-tf32
// grid = (N/128, M/128, ndir); 256 threads; warp tile 64x32
struct GArgs {
    const float* A[2]; const float* B[2]; const float* bias[2]; float* C[2];
    int revA[2], revC[2], colOff[2];
    int lda, ldb, ldc, M, K;
};

#define TG_STAGE_F 8960                    // floats per stage (As 128*36 + Bs 32*136)
#define TG_SMEM    (2 * TG_STAGE_F * 4)    // 71680 bytes

template <int EPI>
__global__ __launch_bounds__(256, 2)
void tgemm_ca(GArgs ga)
{
    extern __shared__ float smem[];

    const int tid  = threadIdx.x;
    const int lane = tid & 31;
    const int warp = tid >> 5;
    const int wm = warp & 1;
    const int wn = warp >> 1;
    const int g  = lane >> 2;
    const int cc = lane & 3;
    const int bx = blockIdx.x, by = blockIdx.y;
    const int dz = blockIdx.z;

    const float* A = ga.A[dz];
    const float* B = ga.B[dz];
    const float* bias = ga.bias[dz];
    float* C = ga.C[dz];
    const int revA = ga.revA[dz], revC = ga.revC[dz], colOff = ga.colOff[dz];
    const int lda = ga.lda, ldb = ga.ldb, ldc = ga.ldc, M = ga.M, K = ga.K;

    // ---- cp.async copy mapping: 4 A-chunks + 4 B-chunks of 16B per thread ----
    const float* aSrc[4]; int aDst[4];     // smem float offsets within stage
    const float* bSrc[4]; int bDst[4];
    #pragma unroll
    for (int i = 0; i < 4; i++) {
        int c = tid * 4 + i;               // 0..1023
        int arow = c >> 3, akq = c & 7;
        int grow = by * 128 + arow;
        if (revA) grow = M - 1 - grow;
        aSrc[i] = A + (size_t)grow * lda + akq * 4;
        aDst[i] = arow * 36 + akq * 4;
        int bk = c >> 5, bnq = c & 31;
        bSrc[i] = B + (size_t)bk * ldb + bx * 128 + bnq * 4;
        bDst[i] = 128 * 36 + bk * 136 + bnq * 4;
    }

    float acc[4][4][4];
    #pragma unroll
    for (int mt = 0; mt < 4; mt++)
        #pragma unroll
        for (int nt = 0; nt < 4; nt++)
            #pragma unroll
            for (int i = 0; i < 4; i++) acc[mt][nt][i] = 0.f;

    auto issue = [&](int k0, int st) {
        float* base = smem + st * TG_STAGE_F;
        #pragma unroll
        for (int i = 0; i < 4; i++) cpa16(base + aDst[i], aSrc[i] + k0);
        #pragma unroll
        for (int i = 0; i < 4; i++) cpa16(base + bDst[i], bSrc[i] + (size_t)k0 * ldb);
        cpa_commit();
    };

    issue(0, 0);

    const int nIt = K / 32;
    for (int it = 0; it < nIt; ++it) {
        const int p = it & 1;
        cpa_wait0();
        __syncthreads();
        if (it + 1 < nIt) issue((it + 1) * 32, 1 - p);

        const float* As = smem + p * TG_STAGE_F;
        const float* Bs = As + 128 * 36;
        #pragma unroll
        for (int ks = 0; ks < 32; ks += 8) {
            uint32_t a[4][4], b[4][2];
            #pragma unroll
            for (int mt = 0; mt < 4; mt++) {
                const float* p0 = &As[(wm * 64 + mt * 16 + g) * 36 + ks + cc];
                const float* p1 = &As[(wm * 64 + mt * 16 + g + 8) * 36 + ks + cc];
                a[mt][0] = __float_as_uint(p0[0]); a[mt][2] = __float_as_uint(p0[4]);
                a[mt][1] = __float_as_uint(p1[0]); a[mt][3] = __float_as_uint(p1[4]);
            }
            #pragma unroll
            for (int nt = 0; nt < 4; nt++) {
                b[nt][0] = __float_as_uint(Bs[(ks + cc) * 136 + wn * 32 + nt * 8 + g]);
                b[nt][1] = __float_as_uint(Bs[(ks + cc + 4) * 136 + wn * 32 + nt * 8 + g]);
            }
            #pragma unroll
            for (int mt = 0; mt < 4; mt++)
                #pragma unroll
                for (int nt = 0; nt < 4; nt++)
                    mma_tf32(acc[mt][nt], a[mt], b[nt]);
        }
        __syncthreads();
    }

    // ---- epilogue ----
    #pragma unroll
    for (int mt = 0; mt < 4; mt++) {
        int r0 = by * 128 + wm * 64 + mt * 16 + g;
        int r1 = r0 + 8;
        int or0 = revC ? (M - 1 - r0) : r0;
        int or1 = revC ? (M - 1 - r1) : r1;
        float* crow0 = C + (size_t)or0 * ldc + colOff;
        float* crow1 = C + (size_t)or1 * ldc + colOff;
        #pragma unroll
        for (int nt = 0; nt < 4; nt++) {
            int col = bx * 128 + wn * 32 + nt * 8 + 2 * cc;
            float b0 = bias[col], b1 = bias[col + 1];
            float v00 = acc[mt][nt][0] + b0, v01 = acc[mt][nt][1] + b1;
            float v10 = acc[mt][nt][2] + b0, v11 = acc[mt][nt][3] + b1;
            if (EPI == 1) {
                v00 = (v00 > 15.f) ? v00 : log1pf(__expf(v00));
                v01 = (v01 > 15.f) ? v01 : log1pf(__expf(v01));
                v10 = (v10 > 15.f) ? v10 : log1pf(__expf(v10));
                v11 = (v11 > 15.f) ? v11 : log1pf(__expf(v11));
            }
            if (EPI == 2) {
                v00 = __uint_as_float(f2t(v00)); v01 = __uint_as_float(f2t(v01));
                v10 = __uint_as_float(f2t(v10)); v11 = __uint_as_float(f2t(v11));
            }
            *(float2*)&crow0[col] = make_float2(v00, v01);
            *(float2*)&crow1[col] = make_float2(v10, v11);
        }
    }
}

// ------------------------- small N=32 GEMM (B,C projection), both dirs -----
__global__ void sgemm_n32b(const float* __restrict__ xpb0,
                           const float* __restrict__ xpb1)
{
    const int dir = blockIdx.y;
    const float* A = g_sxc[dir];
    const float* B = g_wr + (dir ? OFF_XPW1 : OFF_XPW0) + DI;  // rounded
    const float* bias = (dir ? xpb1 : xpb0) + DI;
    float* C = g_BC[dir];

    __shared__ float Bs[32][33];
    __shared__ float As[8][33];
    const int r = threadIdx.x >> 5;
    const int c = threadIdx.x & 31;
    const int row0 = blockIdx.x * 8;
    float acc = 0.f;
    for (int k0 = 0; k0 < DI; k0 += 32) {
        #pragma unroll
        for (int i = r; i < 32; i += 8) Bs[i][c] = B[(size_t)(k0 + i) * 1056 + c];
        As[r][c] = A[(size_t)(row0 + r) * DI + k0 + c];
        __syncthreads();
        #pragma unroll
        for (int kk = 0; kk < 32; kk++) acc += As[r][kk] * Bs[kk][c];
        __syncthreads();
    }
    C[(size_t)(row0 + r) * 32 + c] = acc + bias[c];
}

// ------------------------- causal depthwise conv (K=4) + silu -------------
__global__ void conv_silu_kernel(const float* __restrict__ cw_f,
                                 const float* __restrict__ cb_f,
                                 const float* __restrict__ cw_b,
                                 const float* __restrict__ cb_b)
{
    const int dir = blockIdx.z;
    const int idx = blockIdx.x * blockDim.x + threadIdx.x;
    const int l = idx >> 10;
    const int d = idx & (DI - 1);
    const float* xz = g_xz[dir];
    const float* w = dir ? cw_b : cw_f;
    const float* b = dir ? cb_b : cb_f;
    float s = b[d];
    #pragma unroll
    for (int k = 0; k < 4; k++) {
        int ls = l - 3 + k;
        if (ls >= 0) s += xz[(size_t)ls * (2 * DI) + d] * w[d * 4 + k];
    }
    g_xc[dir][idx] = s;
    float sil = s / (1.f + __expf(-s));
    g_sxc[dir][idx] = __uint_as_float(f2t(sil));
}

// ------------------------- chunked scan --------------------------------
__global__ void scan_phaseA(const float* __restrict__ A_log)
{
    const int dir = blockIdx.z;
    const int s = threadIdx.x & 15;
    const int dl = threadIdx.x >> 4;
    const int d = blockIdx.y * 16 + dl;
    const int c = blockIdx.x;
    const float Av = -__expf(A_log[d * NST + s]);
    const float* dtp = g_dt[dir];
    const float* xp = g_xc[dir];
    const float* bc = g_BC[dir];
    float h = 0.f, ap = 1.f;
    int l = c * TCH;
    #pragma unroll 4
    for (int t = 0; t < TCH; t++, l++) {
        float dtv = dtp[l * DI + d];
        float xv = xp[l * DI + d];
        float Bv = bc[l * 32 + s];
        float a = __expf(dtv * Av);
        h = a * h + dtv * Bv * xv;
        ap *= a;
    }
    const int o = (c << 14) + (d << 4) + s;
    g_aprod[dir][o] = ap;
    g_hpart[dir][o] = h;
}

__global__ void scan_phaseB()
{
    const int idx = blockIdx.x * blockDim.x + threadIdx.x;
    const int dir = idx >> 14;
    const int ds = idx & 16383;
    float h = 0.f;
    for (int c = 0; c < NC; c++) {
        const int o = (c << 14) + ds;
        g_hinit[dir][o] = h;
        h = g_aprod[dir][o] * h + g_hpart[dir][o];
    }
}

__global__ void scan_phaseC(const float* __restrict__ A_log,
                            const float* __restrict__ Dp)
{
    const int dir = blockIdx.z;
    const int s = threadIdx.x & 15;
    const int dl = threadIdx.x >> 4;
    const int d = blockIdx.y * 16 + dl;
    const int c = blockIdx.x;
    const float Av = -__expf(A_log[d * NST + s]);
    const float Dv = Dp[d];
    const float* dtp = g_dt[dir];
    const float* xp = g_xc[dir];
    const float* bc = g_BC[dir];
    const float* xz = g_xz[dir];
    float h = g_hinit[dir][(c << 14) + (d << 4) + s];
    int l = c * TCH;
    for (int t = 0; t < TCH; t++, l++) {
        float dtv = dtp[l * DI + d];
        float xv = xp[l * DI + d];
        float Bv = bc[l * 32 + s];
        float Cv = bc[l * 32 + 16 + s];
        float a = __expf(dtv * Av);
        h = a * h + dtv * Bv * xv;
        float val = h * Cv;
        val += __shfl_xor_sync(0xffffffffu, val, 1);
        val += __shfl_xor_sync(0xffffffffu, val, 2);
        val += __shfl_xor_sync(0xffffffffu, val, 4);
        val += __shfl_xor_sync(0xffffffffu, val, 8);
        if (s == 0) {
            float y = val + Dv * xv;
            float zv = xz[(size_t)l * (2 * DI) + DI + d];
            float u = y * (zv / (1.f + __expf(-zv)));
            g_u[dir][l * DI + d] = __uint_as_float(f2t(u));
        }
    }
}

// ------------------------- host launcher --------------------------------
extern "C" void kernel_launch(void* const* d_in, const int* in_sizes, int n_in,
                              void* d_out, int out_size)
{
    (void)in_sizes; (void)n_in; (void)out_size;
    const float* x = (const float*)d_in[0];
    const float* inW[2]  = { (const float*)d_in[1],  (const float*)d_in[11] };
    const float* inb[2]  = { (const float*)d_in[2],  (const float*)d_in[12] };
    const float* cw[2]   = { (const float*)d_in[3],  (const float*)d_in[13] };
    const float* cb[2]   = { (const float*)d_in[4],  (const float*)d_in[14] };
    const float* xpW[2]  = { (const float*)d_in[5],  (const float*)d_in[15] };
    const float* xpb[2]  = { (const float*)d_in[6],  (const float*)d_in[16] };
    const float* dtW[2]  = { (const float*)d_in[7],  (const float*)d_in[17] };
    const float* dtb[2]  = { (const float*)d_in[8],  (const float*)d_in[18] };
    const float* outW[2] = { (const float*)d_in[9],  (const float*)d_in[19] };
    const float* outb[2] = { (const float*)d_in[10], (const float*)d_in[20] };
    const float* A_log   = (const float*)d_in[21];
    const float* Dp      = (const float*)d_in[22];
    const float* fuW     = (const float*)d_in[23];
    const float* fub     = (const float*)d_in[24];
    float* out = (float*)d_out;

    float *xz, *delta, *ub, *catb, *wr;
    cudaGetSymbolAddress((void**)&xz,    g_xz);
    cudaGetSymbolAddress((void**)&delta, g_delta);
    cudaGetSymbolAddress((void**)&ub,    g_u);
    cudaGetSymbolAddress((void**)&catb,  g_cat);
    cudaGetSymbolAddress((void**)&wr,    g_wr);
    float* sxc;
    cudaGetSymbolAddress((void**)&sxc,   g_sxc);
    float* dtbuf;
    cudaGetSymbolAddress((void**)&dtbuf, g_dt);

    cudaFuncSetAttribute(tgemm_ca<0>, cudaFuncAttributeMaxDynamicSharedMemorySize, TG_SMEM);
    cudaFuncSetAttribute(tgemm_ca<1>, cudaFuncAttributeMaxDynamicSharedMemorySize, TG_SMEM);
    cudaFuncSetAttribute(tgemm_ca<2>, cudaFuncAttributeMaxDynamicSharedMemorySize, TG_SMEM);

    const dim3 blk(256);

    // 0. round x + weights to tf32
    {
        RArgs ra;
        ra.s[0] = x;       ra.d[0] = wr + OFF_X;     ra.n[0] = L * DM;
        ra.s[1] = inW[0];  ra.d[1] = wr + OFF_INW0;  ra.n[1] = DM * 2 * DI;
        ra.s[2] = inW[1];  ra.d[2] = wr + OFF_INW1;  ra.n[2] = DM * 2 * DI;
        ra.s[3] = xpW[0];  ra.d[3] = wr + OFF_XPW0;  ra.n[3] = DI * 1056;
        ra.s[4] = xpW[1];  ra.d[4] = wr + OFF_XPW1;  ra.n[4] = DI * 1056;
        ra.s[5] = dtW[0];  ra.d[5] = wr + OFF_DTW0;  ra.n[5] = DI * DI;
        ra.s[6] = dtW[1];  ra.d[6] = wr + OFF_DTW1;  ra.n[6] = DI * DI;
        ra.s[7] = outW[0]; ra.d[7] = wr + OFF_OUTW0; ra.n[7] = DI * DM;
        ra.s[8] = outW[1]; ra.d[8] = wr + OFF_OUTW1; ra.n[8] = DI * DM;
        ra.s[9] = fuW;     ra.d[9] = wr + OFF_FUW;   ra.n[9] = 2 * DM * DM;
        int mx = DI * 1056 / 4;
        round_tf32_kernel<<<dim3((mx + 255) / 256, 10), blk>>>(ra);
    }

    // 1. in-projection (both dirs): xz[dir] = x(rev) @ inW + inb
    {
        GArgs ga{};
        for (int d2 = 0; d2 < 2; d2++) {
            ga.A[d2] = wr + OFF_X;
            ga.B[d2] = wr + (d2 ? OFF_INW1 : OFF_INW0);
            ga.bias[d2] = inb[d2];
            ga.C[d2] = xz + (size_t)d2 * L * 2 * DI;
            ga.revA[d2] = d2; ga.revC[d2] = 0; ga.colOff[d2] = 0;
        }
        ga.lda = DM; ga.ldb = 2 * DI; ga.ldc = 2 * DI; ga.M = L; ga.K = DM;
        tgemm_ca<0><<<dim3(2 * DI / 128, L / 128, 2), blk, TG_SMEM>>>(ga);
    }

    // 2. causal conv + silu (sxc rounded)
    conv_silu_kernel<<<dim3(L * DI / 256, 1, 2), blk>>>(cw[0], cb[0], cw[1], cb[1]);

    // 3a. xp projection, delta part (both dirs)
    {
        GArgs ga{};
        for (int d2 = 0; d2 < 2; d2++) {
            ga.A[d2] = sxc + (size_t)d2 * L * DI;
            ga.B[d2] = wr + (d2 ? OFF_XPW1 : OFF_XPW0);
            ga.bias[d2] = xpb[d2];
            ga.C[d2] = delta + (size_t)d2 * L * DI;
            ga.revA[d2] = 0; ga.revC[d2] = 0; ga.colOff[d2] = 0;
        }
        ga.lda = DI; ga.ldb = 1056; ga.ldc = DI; ga.M = L; ga.K = DI;
        tgemm_ca<2><<<dim3(DI / 128, L / 128, 2), blk, TG_SMEM>>>(ga);
    }
    // 3b. BC part (both dirs)
    sgemm_n32b<<<dim3(L / 8, 2), blk>>>(xpb[0], xpb[1]);

    // 4. dt = softplus(delta @ dtW + dtb) (both dirs)
    {
        GArgs ga{};
        for (int d2 = 0; d2 < 2; d2++) {
            ga.A[d2] = delta + (size_t)d2 * L * DI;
            ga.B[d2] = wr + (d2 ? OFF_DTW1 : OFF_DTW0);
            ga.bias[d2] = dtb[d2];
            ga.C[d2] = dtbuf + (size_t)d2 * L * DI;
            ga.revA[d2] = 0; ga.revC[d2] = 0; ga.colOff[d2] = 0;
        }
        ga.lda = DI; ga.ldb = DI; ga.ldc = DI; ga.M = L; ga.K = DI;
        tgemm_ca<1><<<dim3(DI / 128, L / 128, 2), blk, TG_SMEM>>>(ga);
    }

    // 5. chunked selective scan -> u = y * silu(z)  (u rounded)
    scan_phaseA<<<dim3(NC, DI / 16, 2), blk>>>(A_log);
    scan_phaseB<<<2 * DI * NST / 256, blk>>>();
    scan_phaseC<<<dim3(NC, DI / 16, 2), blk>>>(A_log, Dp);

    // 6. out projection -> cat buffer (both dirs; bwd reversed, colOff 512)
    {
        GArgs ga{};
        for (int d2 = 0; d2 < 2; d2++) {
            ga.A[d2] = ub + (size_t)d2 * L * DI;
            ga.B[d2] = wr + (d2 ? OFF_OUTW1 : OFF_OUTW0);
            ga.bias[d2] = outb[d2];
            ga.C[d2] = catb;
            ga.revA[d2] = 0; ga.revC[d2] = d2; ga.colOff[d2] = d2 * DM;
        }
        ga.lda = DI; ga.ldb = DM; ga.ldc = 2 * DM; ga.M = L; ga.K = DI;
        tgemm_ca<2><<<dim3(DM / 128, L / 128, 2), blk, TG_SMEM>>>(ga);
    }

    // 7. fusion: out = cat @ fusion_W + fusion_b
    {
        GArgs ga{};
        ga.A[0] = catb; ga.B[0] = wr + OFF_FUW; ga.bias[0] = fub; ga.C[0] = out;
        ga.revA[0] = 0; ga.revC[0] = 0; ga.colOff[0] = 0;
        ga.A[1] = catb; ga.B[1] = wr + OFF_FUW; ga.bias[1] = fub; ga.C[1] = out;
        ga.revA[1] = 0; ga.revC[1] = 0; ga.colOff[1] = 0;
        ga.lda = 2 * DM; ga.ldb = DM; ga.ldc = DM; ga.M = L; ga.K = 2 * DM;
        tgemm_ca<0><<<dim3(DM / 128, L / 128, 1), blk, TG_SMEM>>>(ga);
    }
}

// round 4
// speedup vs baseline: 2.8850x; 1.1605x over previous
#include <cuda_runtime.h>
#include <cuda_bf16.h>
#include <cstdint>

#define L      2048
#define DM     512
#define DI     1024
#define NST    16
#define NC     64           // scan chunks
#define TCH    (L / NC)     // 32 steps per chunk

// ------------------------- scratch (__device__ globals, no alloc) ----------
__device__ float g_xz[2][L * 2 * DI];        // in-proj output per dir
__device__ float g_xc[2][L * DI];            // conv output
__device__ float g_sxc[2][L * DI];           // silu(conv) [tf32-rounded]
__device__ float g_delta[2][L * DI];         // sp[:, :1024] [tf32-rounded]
__device__ float g_BC[2][L * 32];            // sp[:, 1024:1056] (B|C)
__device__ float g_dt[2][L * DI];            // softplus(delta@dtW+b)
__device__ float g_u[2][L * DI];             // y * silu(z) [tf32-rounded]
__device__ float g_cat[L * 2 * DM];          // [out_fwd | out_bwd(rev)] [rounded]
__device__ float g_aprod[2][NC * DI * NST];
__device__ float g_hpart[2][NC * DI * NST];
__device__ float g_hinit[2][NC * DI * NST];

// tf32-rounded copies of x + weights
#define OFF_X      0
#define OFF_INW0   (OFF_X    + L * DM)
#define OFF_INW1   (OFF_INW0 + DM * 2 * DI)
#define OFF_XPW0   (OFF_INW1 + DM * 2 * DI)
#define OFF_XPW1   (OFF_XPW0 + DI * 1056)
#define OFF_DTW0   (OFF_XPW1 + DI * 1056)
#define OFF_DTW1   (OFF_DTW0 + DI * DI)
#define OFF_OUTW0  (OFF_DTW1 + DI * DI)
#define OFF_OUTW1  (OFF_OUTW0 + DI * DM)
#define OFF_FUW    (OFF_OUTW1 + DI * DM)
#define WR_TOTAL   (OFF_FUW   + 2 * DM * DM)
__device__ float g_wr[WR_TOTAL];

// ------------------------- tf32 helpers -----------------------------------
__device__ __forceinline__ uint32_t f2t(float f) {
    uint32_t u;
    asm("cvt.rna.tf32.f32 %0, %1;" : "=r"(u) : "f"(f));
    return u;
}

__device__ __forceinline__ void mma_tf32(float* c, const uint32_t* a, const uint32_t* b) {
    asm volatile(
        "mma.sync.aligned.m16n8k8.row.col.f32.tf32.tf32.f32 "
        "{%0,%1,%2,%3}, {%4,%5,%6,%7}, {%8,%9}, {%0,%1,%2,%3};\n"
        : "+f"(c[0]), "+f"(c[1]), "+f"(c[2]), "+f"(c[3])
        : "r"(a[0]), "r"(a[1]), "r"(a[2]), "r"(a[3]), "r"(b[0]), "r"(b[1]));
}

__device__ __forceinline__ void cpa16(float* s, const float* g) {
    uint32_t sa = (uint32_t)__cvta_generic_to_shared(s);
    asm volatile("cp.async.cg.shared.global [%0], [%1], 16;" :: "r"(sa), "l"(g));
}
__device__ __forceinline__ void cpa_commit() {
    asm volatile("cp.async.commit_group;" ::: "memory");
}
__device__ __forceinline__ void cpa_wait0() {
    asm volatile("cp.async.wait_group 0;" ::: "memory");
}

// ------------------------- round-to-tf32 pre-pass --------------------------
struct RArgs { const float* s[10]; float* d[10]; int n[10]; };

__global__ void round_tf32_kernel(RArgs ra)
{
    const int e = blockIdx.y;
    const int i = (blockIdx.x * 256 + threadIdx.x) * 4;
    if (i >= ra.n[e]) return;
    float4 v = *(const float4*)(ra.s[e] + i);
    uint4 u = make_uint4(f2t(v.x), f2t(v.y), f2t(v.z), f2t(v.w));
    *(uint4*)(ra.d[e] + i) = u;
}

// ------------------------- tensor-core GEMM (cp.async pipelined) -----------
// EPI: 0=none, 1=softplus, 2=round-to-tf32
// CTA tile 128(M) x 64(N), 128 threads (4 warps, 2x2), warp tile 64x32
// grid = (N/64, M/128, ndir)
struct GArgs {
    const float* A[2]; const float* B[2]; const float* bias[2]; float* C[2];
    int revA[2], revC[2], colOff[2];
    int lda, ldb, ldc, M, K;
};

#define TG_STAGE_F 6912                    // As 128*36 + Bs 32*72
#define TG_SMEM    (2 * TG_STAGE_F * 4)    // 55296 bytes

template <int EPI>
__global__ __launch_bounds__(128, 4)
void tgemm_ca(GArgs ga)
{
    extern __shared__ float smem[];

    const int tid  = threadIdx.x;
    const int lane = tid & 31;
    const int warp = tid >> 5;
    const int wm = warp & 1;      // M half (0/1 -> 0/64)
    const int wn = warp >> 1;     // N half (0/1 -> 0/32)
    const int g  = lane >> 2;
    const int cc = lane & 3;
    const int bx = blockIdx.x, by = blockIdx.y;
    const int dz = blockIdx.z;

    const float* A = ga.A[dz];
    const float* B = ga.B[dz];
    const float* bias = ga.bias[dz];
    float* C = ga.C[dz];
    const int revA = ga.revA[dz], revC = ga.revC[dz], colOff = ga.colOff[dz];
    const int lda = ga.lda, ldb = ga.ldb, ldc = ga.ldc, M = ga.M, K = ga.K;

    // ---- cp.async mapping ----
    // A: 1024 floats4-chunks? 128 rows x 32 K-floats = 1024 chunks? -> 8 per thread
    //    thread t: rows r0 + 16*j (j<8), K-quad akq
    const int r0  = tid >> 3;          // 0..15
    const int akq = tid & 7;           // 0..7
    int grow0 = by * 128 + r0;
    long aStep;
    const float* aBase;
    if (revA) { grow0 = M - 1 - grow0; aStep = -16L * lda; }
    else      { aStep =  16L * lda; }
    aBase = A + (size_t)grow0 * lda + akq * 4;
    const int aDst0 = r0 * 36 + akq * 4;
    // B: 32 K-rows x 64 N-floats = 512 chunks -> 4 per thread
    //    thread t: K-rows bk0 + 8*j (j<4), N-quad bnq
    const int bk0 = tid >> 4;          // 0..7
    const int bnq = tid & 15;          // 0..15
    const float* bBase = B + (size_t)bk0 * ldb + bx * 64 + bnq * 4;
    const int bDst0 = 128 * 36 + bk0 * 72 + bnq * 4;

    float acc[4][4][4];
    #pragma unroll
    for (int mt = 0; mt < 4; mt++)
        #pragma unroll
        for (int nt = 0; nt < 4; nt++)
            #pragma unroll
            for (int i = 0; i < 4; i++) acc[mt][nt][i] = 0.f;

    auto issue = [&](int k0, int st) {
        float* base = smem + st * TG_STAGE_F;
        #pragma unroll
        for (int j = 0; j < 8; j++)
            cpa16(base + aDst0 + j * (16 * 36), aBase + k0 + j * aStep);
        #pragma unroll
        for (int j = 0; j < 4; j++)
            cpa16(base + bDst0 + j * (8 * 72), bBase + (size_t)(k0 + 8 * j) * ldb);
        cpa_commit();
    };

    issue(0, 0);

    const int nIt = K / 32;
    for (int it = 0; it < nIt; ++it) {
        const int p = it & 1;
        cpa_wait0();
        __syncthreads();
        if (it + 1 < nIt) issue((it + 1) * 32, 1 - p);

        const float* As = smem + p * TG_STAGE_F;
        const float* Bs = As + 128 * 36;
        #pragma unroll
        for (int ks = 0; ks < 32; ks += 8) {
            uint32_t a[4][4], b[4][2];
            #pragma unroll
            for (int mt = 0; mt < 4; mt++) {
                const float* p0 = &As[(wm * 64 + mt * 16 + g) * 36 + ks + cc];
                const float* p1 = &As[(wm * 64 + mt * 16 + g + 8) * 36 + ks + cc];
                a[mt][0] = __float_as_uint(p0[0]); a[mt][2] = __float_as_uint(p0[4]);
                a[mt][1] = __float_as_uint(p1[0]); a[mt][3] = __float_as_uint(p1[4]);
            }
            #pragma unroll
            for (int nt = 0; nt < 4; nt++) {
                b[nt][0] = __float_as_uint(Bs[(ks + cc) * 72 + wn * 32 + nt * 8 + g]);
                b[nt][1] = __float_as_uint(Bs[(ks + cc + 4) * 72 + wn * 32 + nt * 8 + g]);
            }
            #pragma unroll
            for (int mt = 0; mt < 4; mt++)
                #pragma unroll
                for (int nt = 0; nt < 4; nt++)
                    mma_tf32(acc[mt][nt], a[mt], b[nt]);
        }
        __syncthreads();
    }

    // ---- epilogue ----
    #pragma unroll
    for (int mt = 0; mt < 4; mt++) {
        int rr0 = by * 128 + wm * 64 + mt * 16 + g;
        int rr1 = rr0 + 8;
        int or0 = revC ? (M - 1 - rr0) : rr0;
        int or1 = revC ? (M - 1 - rr1) : rr1;
        float* crow0 = C + (size_t)or0 * ldc + colOff;
        float* crow1 = C + (size_t)or1 * ldc + colOff;
        #pragma unroll
        for (int nt = 0; nt < 4; nt++) {
            int col = bx * 64 + wn * 32 + nt * 8 + 2 * cc;
            float b0 = bias[col], b1 = bias[col + 1];
            float v00 = acc[mt][nt][0] + b0, v01 = acc[mt][nt][1] + b1;
            float v10 = acc[mt][nt][2] + b0, v11 = acc[mt][nt][3] + b1;
            if (EPI == 1) {
                v00 = (v00 > 15.f) ? v00 : log1pf(__expf(v00));
                v01 = (v01 > 15.f) ? v01 : log1pf(__expf(v01));
                v10 = (v10 > 15.f) ? v10 : log1pf(__expf(v10));
                v11 = (v11 > 15.f) ? v11 : log1pf(__expf(v11));
            }
            if (EPI == 2) {
                v00 = __uint_as_float(f2t(v00)); v01 = __uint_as_float(f2t(v01));
                v10 = __uint_as_float(f2t(v10)); v11 = __uint_as_float(f2t(v11));
            }
            *(float2*)&crow0[col] = make_float2(v00, v01);
            *(float2*)&crow1[col] = make_float2(v10, v11);
        }
    }
}

// ------------------------- small N=32 GEMM (B,C projection), both dirs -----
__global__ void sgemm_n32b(const float* __restrict__ xpb0,
                           const float* __restrict__ xpb1)
{
    const int dir = blockIdx.y;
    const float* A = g_sxc[dir];
    const float* B = g_wr + (dir ? OFF_XPW1 : OFF_XPW0) + DI;  // rounded
    const float* bias = (dir ? xpb1 : xpb0) + DI;
    float* C = g_BC[dir];

    __shared__ float Bs[32][33];
    __shared__ float As[8][33];
    const int r = threadIdx.x >> 5;
    const int c = threadIdx.x & 31;
    const int row0 = blockIdx.x * 8;
    float acc = 0.f;
    for (int k0 = 0; k0 < DI; k0 += 32) {
        #pragma unroll
        for (int i = r; i < 32; i += 8) Bs[i][c] = B[(size_t)(k0 + i) * 1056 + c];
        As[r][c] = A[(size_t)(row0 + r) * DI + k0 + c];
        __syncthreads();
        #pragma unroll
        for (int kk = 0; kk < 32; kk++) acc += As[r][kk] * Bs[kk][c];
        __syncthreads();
    }
    C[(size_t)(row0 + r) * 32 + c] = acc + bias[c];
}

// ------------------------- causal depthwise conv (K=4) + silu -------------
__global__ void conv_silu_kernel(const float* __restrict__ cw_f,
                                 const float* __restrict__ cb_f,
                                 const float* __restrict__ cw_b,
                                 const float* __restrict__ cb_b)
{
    const int dir = blockIdx.z;
    const int idx = blockIdx.x * blockDim.x + threadIdx.x;
    const int l = idx >> 10;
    const int d = idx & (DI - 1);
    const float* xz = g_xz[dir];
    const float* w = dir ? cw_b : cw_f;
    const float* b = dir ? cb_b : cb_f;
    float s = b[d];
    #pragma unroll
    for (int k = 0; k < 4; k++) {
        int ls = l - 3 + k;
        if (ls >= 0) s += xz[(size_t)ls * (2 * DI) + d] * w[d * 4 + k];
    }
    g_xc[dir][idx] = s;
    float sil = s / (1.f + __expf(-s));
    g_sxc[dir][idx] = __uint_as_float(f2t(sil));
}

// ------------------------- chunked scan --------------------------------
__global__ void scan_phaseA(const float* __restrict__ A_log)
{
    const int dir = blockIdx.z;
    const int s = threadIdx.x & 15;
    const int dl = threadIdx.x >> 4;
    const int d = blockIdx.y * 16 + dl;
    const int c = blockIdx.x;
    const float Av = -__expf(A_log[d * NST + s]);
    const float* dtp = g_dt[dir];
    const float* xp = g_xc[dir];
    const float* bc = g_BC[dir];
    float h = 0.f, ap = 1.f;
    int l = c * TCH;
    #pragma unroll 4
    for (int t = 0; t < TCH; t++, l++) {
        float dtv = dtp[l * DI + d];
        float xv = xp[l * DI + d];
        float Bv = bc[l * 32 + s];
        float a = __expf(dtv * Av);
        h = a * h + dtv * Bv * xv;
        ap *= a;
    }
    const int o = (c << 14) + (d << 4) + s;
    g_aprod[dir][o] = ap;
    g_hpart[dir][o] = h;
}

__global__ void scan_phaseB()
{
    const int idx = blockIdx.x * blockDim.x + threadIdx.x;
    const int dir = idx >> 14;
    const int ds = idx & 16383;
    float h = 0.f;
    for (int c = 0; c < NC; c++) {
        const int o = (c << 14) + ds;
        g_hinit[dir][o] = h;
        h = g_aprod[dir][o] * h + g_hpart[dir][o];
    }
}

__global__ void scan_phaseC(const float* __restrict__ A_log,
                            const float* __restrict__ Dp)
{
    const int dir = blockIdx.z;
    const int s = threadIdx.x & 15;
    const int dl = threadIdx.x >> 4;
    const int d = blockIdx.y * 16 + dl;
    const int c = blockIdx.x;
    const float Av = -__expf(A_log[d * NST + s]);
    const float Dv = Dp[d];
    const float* dtp = g_dt[dir];
    const float* xp = g_xc[dir];
    const float* bc = g_BC[dir];
    const float* xz = g_xz[dir];
    float h = g_hinit[dir][(c << 14) + (d << 4) + s];
    int l = c * TCH;
    for (int t = 0; t < TCH; t++, l++) {
        float dtv = dtp[l * DI + d];
        float xv = xp[l * DI + d];
        float Bv = bc[l * 32 + s];
        float Cv = bc[l * 32 + 16 + s];
        float a = __expf(dtv * Av);
        h = a * h + dtv * Bv * xv;
        float val = h * Cv;
        val += __shfl_xor_sync(0xffffffffu, val, 1);
        val += __shfl_xor_sync(0xffffffffu, val, 2);
        val += __shfl_xor_sync(0xffffffffu, val, 4);
        val += __shfl_xor_sync(0xffffffffu, val, 8);
        if (s == 0) {
            float y = val + Dv * xv;
            float zv = xz[(size_t)l * (2 * DI) + DI + d];
            float u = y * (zv / (1.f + __expf(-zv)));
            g_u[dir][l * DI + d] = __uint_as_float(f2t(u));
        }
    }
}

// ------------------------- host launcher --------------------------------
extern "C" void kernel_launch(void* const* d_in, const int* in_sizes, int n_in,
                              void* d_out, int out_size)
{
    (void)in_sizes; (void)n_in; (void)out_size;
    const float* x = (const float*)d_in[0];
    const float* inW[2]  = { (const float*)d_in[1],  (const float*)d_in[11] };
    const float* inb[2]  = { (const float*)d_in[2],  (const float*)d_in[12] };
    const float* cw[2]   = { (const float*)d_in[3],  (const float*)d_in[13] };
    const float* cb[2]   = { (const float*)d_in[4],  (const float*)d_in[14] };
    const float* xpW[2]  = { (const float*)d_in[5],  (const float*)d_in[15] };
    const float* xpb[2]  = { (const float*)d_in[6],  (const float*)d_in[16] };
    const float* dtW[2]  = { (const float*)d_in[7],  (const float*)d_in[17] };
    const float* dtb[2]  = { (const float*)d_in[8],  (const float*)d_in[18] };
    const float* outW[2] = { (const float*)d_in[9],  (const float*)d_in[19] };
    const float* outb[2] = { (const float*)d_in[10], (const float*)d_in[20] };
    const float* A_log   = (const float*)d_in[21];
    const float* Dp      = (const float*)d_in[22];
    const float* fuW     = (const float*)d_in[23];
    const float* fub     = (const float*)d_in[24];
    float* out = (float*)d_out;

    float *xz, *delta, *ub, *catb, *wr, *sxc, *dtbuf;
    cudaGetSymbolAddress((void**)&xz,    g_xz);
    cudaGetSymbolAddress((void**)&delta, g_delta);
    cudaGetSymbolAddress((void**)&ub,    g_u);
    cudaGetSymbolAddress((void**)&catb,  g_cat);
    cudaGetSymbolAddress((void**)&wr,    g_wr);
    cudaGetSymbolAddress((void**)&sxc,   g_sxc);
    cudaGetSymbolAddress((void**)&dtbuf, g_dt);

    cudaFuncSetAttribute(tgemm_ca<0>, cudaFuncAttributeMaxDynamicSharedMemorySize, TG_SMEM);
    cudaFuncSetAttribute(tgemm_ca<1>, cudaFuncAttributeMaxDynamicSharedMemorySize, TG_SMEM);
    cudaFuncSetAttribute(tgemm_ca<2>, cudaFuncAttributeMaxDynamicSharedMemorySize, TG_SMEM);

    const dim3 blk(256);
    const dim3 gblk(128);

    // 0. round x + weights to tf32
    {
        RArgs ra;
        ra.s[0] = x;       ra.d[0] = wr + OFF_X;     ra.n[0] = L * DM;
        ra.s[1] = inW[0];  ra.d[1] = wr + OFF_INW0;  ra.n[1] = DM * 2 * DI;
        ra.s[2] = inW[1];  ra.d[2] = wr + OFF_INW1;  ra.n[2] = DM * 2 * DI;
        ra.s[3] = xpW[0];  ra.d[3] = wr + OFF_XPW0;  ra.n[3] = DI * 1056;
        ra.s[4] = xpW[1];  ra.d[4] = wr + OFF_XPW1;  ra.n[4] = DI * 1056;
        ra.s[5] = dtW[0];  ra.d[5] = wr + OFF_DTW0;  ra.n[5] = DI * DI;
        ra.s[6] = dtW[1];  ra.d[6] = wr + OFF_DTW1;  ra.n[6] = DI * DI;
        ra.s[7] = outW[0]; ra.d[7] = wr + OFF_OUTW0; ra.n[7] = DI * DM;
        ra.s[8] = outW[1]; ra.d[8] = wr + OFF_OUTW1; ra.n[8] = DI * DM;
        ra.s[9] = fuW;     ra.d[9] = wr + OFF_FUW;   ra.n[9] = 2 * DM * DM;
        int mx = DI * 1056 / 4;
        round_tf32_kernel<<<dim3((mx + 255) / 256, 10), blk>>>(ra);
    }

    // 1. in-projection (both dirs): xz[dir] = x(rev) @ inW + inb
    {
        GArgs ga{};
        for (int d2 = 0; d2 < 2; d2++) {
            ga.A[d2] = wr + OFF_X;
            ga.B[d2] = wr + (d2 ? OFF_INW1 : OFF_INW0);
            ga.bias[d2] = inb[d2];
            ga.C[d2] = xz + (size_t)d2 * L * 2 * DI;
            ga.revA[d2] = d2; ga.revC[d2] = 0; ga.colOff[d2] = 0;
        }
        ga.lda = DM; ga.ldb = 2 * DI; ga.ldc = 2 * DI; ga.M = L; ga.K = DM;
        tgemm_ca<0><<<dim3(2 * DI / 64, L / 128, 2), gblk, TG_SMEM>>>(ga);
    }

    // 2. causal conv + silu (sxc rounded)
    conv_silu_kernel<<<dim3(L * DI / 256, 1, 2), blk>>>(cw[0], cb[0], cw[1], cb[1]);

    // 3a. xp projection, delta part (both dirs)
    {
        GArgs ga{};
        for (int d2 = 0; d2 < 2; d2++) {
            ga.A[d2] = sxc + (size_t)d2 * L * DI;
            ga.B[d2] = wr + (d2 ? OFF_XPW1 : OFF_XPW0);
            ga.bias[d2] = xpb[d2];
            ga.C[d2] = delta + (size_t)d2 * L * DI;
            ga.revA[d2] = 0; ga.revC[d2] = 0; ga.colOff[d2] = 0;
        }
        ga.lda = DI; ga.ldb = 1056; ga.ldc = DI; ga.M = L; ga.K = DI;
        tgemm_ca<2><<<dim3(DI / 64, L / 128, 2), gblk, TG_SMEM>>>(ga);
    }
    // 3b. BC part (both dirs)
    sgemm_n32b<<<dim3(L / 8, 2), blk>>>(xpb[0], xpb[1]);

    // 4. dt = softplus(delta @ dtW + dtb) (both dirs)
    {
        GArgs ga{};
        for (int d2 = 0; d2 < 2; d2++) {
            ga.A[d2] = delta + (size_t)d2 * L * DI;
            ga.B[d2] = wr + (d2 ? OFF_DTW1 : OFF_DTW0);
            ga.bias[d2] = dtb[d2];
            ga.C[d2] = dtbuf + (size_t)d2 * L * DI;
            ga.revA[d2] = 0; ga.revC[d2] = 0; ga.colOff[d2] = 0;
        }
        ga.lda = DI; ga.ldb = DI; ga.ldc = DI; ga.M = L; ga.K = DI;
        tgemm_ca<1><<<dim3(DI / 64, L / 128, 2), gblk, TG_SMEM>>>(ga);
    }

    // 5. chunked selective scan -> u = y * silu(z)  (u rounded)
    scan_phaseA<<<dim3(NC, DI / 16, 2), blk>>>(A_log);
    scan_phaseB<<<2 * DI * NST / 256, blk>>>();
    scan_phaseC<<<dim3(NC, DI / 16, 2), blk>>>(A_log, Dp);

    // 6. out projection -> cat buffer (both dirs; bwd reversed, colOff 512)
    {
        GArgs ga{};
        for (int d2 = 0; d2 < 2; d2++) {
            ga.A[d2] = ub + (size_t)d2 * L * DI;
            ga.B[d2] = wr + (d2 ? OFF_OUTW1 : OFF_OUTW0);
            ga.bias[d2] = outb[d2];
            ga.C[d2] = catb;
            ga.revA[d2] = 0; ga.revC[d2] = d2; ga.colOff[d2] = d2 * DM;
        }
        ga.lda = DI; ga.ldb = DM; ga.ldc = 2 * DM; ga.M = L; ga.K = DI;
        tgemm_ca<2><<<dim3(DM / 64, L / 128, 2), gblk, TG_SMEM>>>(ga);
    }

    // 7. fusion: out = cat @ fusion_W + fusion_b
    {
        GArgs ga{};
        ga.A[0] = catb; ga.B[0] = wr + OFF_FUW; ga.bias[0] = fub; ga.C[0] = out;
        ga.revA[0] = 0; ga.revC[0] = 0; ga.colOff[0] = 0;
        ga.A[1] = catb; ga.B[1] = wr + OFF_FUW; ga.bias[1] = fub; ga.C[1] = out;
        ga.revA[1] = 0; ga.revC[1] = 0; ga.colOff[1] = 0;
        ga.lda = 2 * DM; ga.ldb = DM; ga.ldc = DM; ga.M = L; ga.K = 2 * DM;
        tgemm_ca<0><<<dim3(DM / 64, L / 128, 1), gblk, TG_SMEM>>>(ga);
    }
}